// round 4
// baseline (speedup 1.0000x reference)
#include <cuda_runtime.h>
#include <cuda_fp16.h>
#include <stdint.h>

#define NS 32
#define TT 2048
#define ND 1024
#define GRID 64
#define NTHREADS 256
#define NWARPS 8
#define KTILES 8     // eight 16-wide k-tiles per warp (8 warps * 8 * 16 = 1024 = K)
#define ROWBLK 32    // rows of A (output neurons) per CTA
#define SBLK 16      // samples per CTA

#define ALPHA 0.1f
#define BETA  0.9f

// Double-buffered fp16 copy of the hidden state, stored in a pre-swizzled
// mma-B-fragment layout.
__device__ __align__(16) __half g_hbuf[2][NS * ND];

// Producer flags: g_flags[sb][rb] holds the number of completed productions
// by CTA (rb, sb). Production 0 = h0 chunk; production t = step-t chunk.
// A consumer at step t needs ALL 32 flags of its sample group >= t.
__device__ __align__(256) volatile unsigned g_flags[2][32];

// Legacy full-grid barrier, used ONCE at kernel end to safely reset flags.
__device__ unsigned g_bar_count;
__device__ unsigned g_bar_gen;

__device__ __forceinline__ void grid_barrier_once() {
    __syncthreads();
    if (threadIdx.x == 0) {
        unsigned gen = *((volatile unsigned*)&g_bar_gen);
        __threadfence();
        unsigned old = atomicAdd(&g_bar_count, 1u);
        if (old == GRID - 1) {
            g_bar_count = 0;
            __threadfence();
            atomicExch(&g_bar_gen, gen + 1u);
        } else {
            while (*((volatile unsigned*)&g_bar_gen) == gen) { }
        }
        __threadfence();
    }
    __syncthreads();
}

__device__ __forceinline__ void mma16816(float* d, const uint32_t* a,
                                         uint32_t b0, uint32_t b1) {
    asm volatile(
        "mma.sync.aligned.m16n8k16.row.col.f32.f16.f16.f32 "
        "{%0,%1,%2,%3}, {%4,%5,%6,%7}, {%8,%9}, {%0,%1,%2,%3};\n"
        : "+f"(d[0]), "+f"(d[1]), "+f"(d[2]), "+f"(d[3])
        : "r"(a[0]), "r"(a[1]), "r"(a[2]), "r"(a[3]), "r"(b0), "r"(b1));
}

// Position of logical element j inside the swizzled per-sample layout.
__device__ __forceinline__ int hpos(int j) {
    int r = j & 15;
    return (j & ~15) + ((r & 6) << 1) + ((r >> 3) << 1) + (r & 1);
}

__device__ __forceinline__ unsigned flag_acquire(const volatile unsigned* p) {
    unsigned v;
    asm volatile("ld.global.acquire.gpu.u32 %0, [%1];"
                 : "=r"(v) : "l"((const unsigned*)p) : "memory");
    return v;
}

__device__ __forceinline__ void flag_release(volatile unsigned* p, unsigned v) {
    asm volatile("st.global.release.gpu.u32 [%0], %1;"
                 :: "l"((unsigned*)p), "r"(v) : "memory");
}

__global__ __launch_bounds__(NTHREADS, 1) void rnn_kernel(
    const float* __restrict__ inp,   // [NS, TT, ND]
    const float* __restrict__ A,     // [ND, ND]
    const float* __restrict__ h0,    // [NS, ND]
    float* __restrict__ out)         // [NS, TT, ND]
{
    __shared__ float psum[NWARPS][SBLK * ROWBLK];  // 16 KB

    const int tid  = threadIdx.x;
    const int w    = tid >> 5;
    const int lane = tid & 31;
    const int g    = lane >> 2;   // groupID
    const int tig  = lane & 3;    // threadID in group

    const int cta  = blockIdx.x;
    const int rb   = cta >> 1;    // 32 row blocks
    const int sb   = cta & 1;     // 2 sample blocks
    const int row0 = rb * ROWBLK;
    const int s0   = sb * SBLK;

    // ---- Load this CTA's A-slice as resident fp16 mma fragments ----
    uint32_t afrag[KTILES][2][4];
#pragma unroll
    for (int kt = 0; kt < KTILES; kt++) {
        int k0 = (w * KTILES + kt) * 16 + 2 * tig;
#pragma unroll
        for (int m = 0; m < 2; m++) {
            const float* p = A + (size_t)(row0 + m * 16 + g) * ND + k0;
            float2 v0 = *(const float2*)(p);
            float2 v1 = *(const float2*)(p + 8 * (size_t)ND);
            float2 v2 = *(const float2*)(p + 8);
            float2 v3 = *(const float2*)(p + 8 * (size_t)ND + 8);
            __half2 q0 = __floats2half2_rn(v0.x, v0.y);
            __half2 q1 = __floats2half2_rn(v1.x, v1.y);
            __half2 q2 = __floats2half2_rn(v2.x, v2.y);
            __half2 q3 = __floats2half2_rn(v3.x, v3.y);
            afrag[kt][m][0] = *(uint32_t*)&q0;
            afrag[kt][m][1] = *(uint32_t*)&q1;
            afrag[kt][m][2] = *(uint32_t*)&q2;
            afrag[kt][m][3] = *(uint32_t*)&q3;
        }
    }

    // ---- Per-thread state ownership: (sample s_l, rows i_l, i_l+1) ----
    const int s_l  = tid >> 4;            // 0..15
    const int i_l  = (tid & 15) << 1;     // 0,2,...,30
    const int s_gl = s0 + s_l;
    const int i_gl = row0 + i_l;
    const int e    = s_l * ROWBLK + i_l;

    const float* inp_base = inp + (size_t)s_gl * TT * ND + i_gl;
    float* out_base       = out + (size_t)s_gl * TT * ND + i_gl;

    // ---- Production 0: h0 chunk ----
    float2 hprev = *(const float2*)(h0 + (size_t)s_gl * ND + i_gl);
    *(float2*)out_base = hprev;
    {
        __half2 hh = __floats2half2_rn(hprev.x, hprev.y);
        *(__half2*)&g_hbuf[0][s_gl * ND + hpos(i_gl)] = hh;
    }
    __syncthreads();
    if (tid == 0) flag_release(&g_flags[sb][rb], 1u);

    // x for step t=1 (uses inp[t-1=0])
    float2 x_cur = __ldcs((const float2*)inp_base);

    for (int t = 1; t < TT; t++) {
        // Prefetch next step's input before blocking on flags (hides DRAM lat).
        float2 x_nxt = make_float2(0.f, 0.f);
        if (t < TT - 1)
            x_nxt = __ldcs((const float2*)(inp_base + (size_t)t * ND));

        // ---- Warp-collective wait: ALL 32 producers of this group >= t ----
        // Each lane polls one producer flag; ballot keeps the warp converged
        // until every lane's flag has arrived (and provides the warp-level
        // memory-ordering hop from each lane's acquire to all lanes' loads).
        {
            const volatile unsigned* f = &g_flags[sb][lane];
            unsigned v = flag_acquire(f);
            while (__ballot_sync(0xffffffffu, v < (unsigned)t)) {
                if (v < (unsigned)t) v = flag_acquire(f);
            }
        }

        const __half* hb = g_hbuf[(t - 1) & 1];

        float d[2][2][4];
#pragma unroll
        for (int m = 0; m < 2; m++)
#pragma unroll
            for (int nu = 0; nu < 2; nu++)
#pragma unroll
                for (int c = 0; c < 4; c++) d[m][nu][c] = 0.0f;

        // ---- GEMM slice: D[i,s] = sum_k A[i,k] * h[s,k] ----
#pragma unroll
        for (int kt = 0; kt < KTILES; kt++) {
            int koff = (w * KTILES + kt) * 16 + tig * 4;
#pragma unroll
            for (int nu = 0; nu < 2; nu++) {
                int s = s0 + nu * 8 + g;
                uint2 b = *(const uint2*)(hb + (size_t)s * ND + koff);
                mma16816(d[0][nu], afrag[kt][0], b.x, b.y);
                mma16816(d[1][nu], afrag[kt][1], b.x, b.y);
            }
        }

        // ---- cross-warp reduction through SMEM ----
#pragma unroll
        for (int m = 0; m < 2; m++)
#pragma unroll
            for (int nu = 0; nu < 2; nu++)
#pragma unroll
                for (int c = 0; c < 4; c++) {
                    int i_loc = m * 16 + g + ((c >> 1) << 3);
                    int s_loc = nu * 8 + tig * 2 + (c & 1);
                    psum[w][s_loc * ROWBLK + i_loc] = d[m][nu][c];
                }
        __syncthreads();

        float sum0 = 0.0f, sum1 = 0.0f;
#pragma unroll
        for (int ww = 0; ww < NWARPS; ww++) {
            float2 p = *(const float2*)&psum[ww][e];
            sum0 += p.x; sum1 += p.y;
        }

        float hn0 = BETA * hprev.x + ALPHA * (sum0 + x_cur.x);
        float hn1 = BETA * hprev.y + ALPHA * (sum1 + x_cur.y);
        hprev.x = hn0; hprev.y = hn1;
        x_cur = x_nxt;

        *(float2*)(out_base + (size_t)t * ND) = make_float2(hn0, hn1);
        __half2 hh = __floats2half2_rn(hn0, hn1);
        *(__half2*)&g_hbuf[t & 1][s_gl * ND + hpos(i_gl)] = hh;

        // ---- Publish production t ----
        __syncthreads();
        if (tid == 0) flag_release(&g_flags[sb][rb], (unsigned)(t + 1));
    }

    // ---- One-time cleanup so graph replays start from flags == 0 ----
    grid_barrier_once();
    if (tid == 0) g_flags[sb][rb] = 0u;
}

extern "C" void kernel_launch(void* const* d_in, const int* in_sizes, int n_in,
                              void* d_out, int out_size) {
    const float* inp = (const float*)d_in[0];
    const float* A   = (const float*)d_in[1];
    const float* h0  = (const float*)d_in[2];
    float* out       = (float*)d_out;
    rnn_kernel<<<GRID, NTHREADS>>>(inp, A, h0, out);
}

// round 5
// speedup vs baseline: 2.8908x; 2.8908x over previous
#include <cuda_runtime.h>
#include <cuda_fp16.h>
#include <stdint.h>

#define NS 32
#define TT 2048
#define ND 1024
#define GRID 64
#define NTHREADS 256
#define NWARPS 8
#define KTILES 8     // 8 warps * 8 ktiles * 16 = 1024 = K
#define ROWBLK 32
#define SBLK 16

#define ALPHA 0.1f
#define BETA  0.9f
#define A2C   (ALPHA * ALPHA)        // alpha^2
#define ABC   (ALPHA * BETA)         // alpha*beta

// Double-buffered fp16 hidden state, pre-swizzled mma-B layout.
__device__ __align__(16) __half g_hbuf[2][NS * ND];
// A@A (row-major fp32), computed once per launch by phase 1.
__device__ float g_A2[ND * ND];
// Producer flags: g_flags[sb][rb] = number of completed hbuf productions.
__device__ __align__(256) volatile unsigned g_flags[2][32];
// Reusable sense-reversing grid barrier.
__device__ unsigned g_bar_count;
__device__ unsigned g_bar_gen;

__device__ __forceinline__ void grid_barrier() {
    __syncthreads();
    if (threadIdx.x == 0) {
        unsigned gen = *((volatile unsigned*)&g_bar_gen);
        __threadfence();
        unsigned old = atomicAdd(&g_bar_count, 1u);
        if (old == GRID - 1) {
            g_bar_count = 0;
            __threadfence();
            atomicExch(&g_bar_gen, gen + 1u);
        } else {
            while (*((volatile unsigned*)&g_bar_gen) == gen) { }
        }
        __threadfence();
    }
    __syncthreads();
}

__device__ __forceinline__ void mma16816(float* d, const uint32_t* a,
                                         uint32_t b0, uint32_t b1) {
    asm volatile(
        "mma.sync.aligned.m16n8k16.row.col.f32.f16.f16.f32 "
        "{%0,%1,%2,%3}, {%4,%5,%6,%7}, {%8,%9}, {%0,%1,%2,%3};\n"
        : "+f"(d[0]), "+f"(d[1]), "+f"(d[2]), "+f"(d[3])
        : "r"(a[0]), "r"(a[1]), "r"(a[2]), "r"(a[3]), "r"(b0), "r"(b1));
}

// Swizzled position of logical element j (per 16-block order 0,1,8,9,2,3,10,11,...)
__device__ __forceinline__ int hpos(int j) {
    int r = j & 15;
    return (j & ~15) + ((r & 6) << 1) + ((r >> 3) << 1) + (r & 1);
}

__device__ __forceinline__ unsigned flag_acquire(const volatile unsigned* p) {
    unsigned v;
    asm volatile("ld.global.acquire.gpu.u32 %0, [%1];"
                 : "=r"(v) : "l"((const unsigned*)p) : "memory");
    return v;
}

__device__ __forceinline__ void flag_release(volatile unsigned* p, unsigned v) {
    asm volatile("st.global.release.gpu.u32 [%0], %1;"
                 :: "l"((unsigned*)p), "r"(v) : "memory");
}

// Load one A-operand fragment set (row-major src, fp32 -> fp16).
__device__ __forceinline__ void load_afrag(uint32_t* f, const float* src,
                                           int row, int k0) {
    const float* p = src + (size_t)row * ND + k0;
    float2 v0 = *(const float2*)(p);
    float2 v1 = *(const float2*)(p + 8 * (size_t)ND);
    float2 v2 = *(const float2*)(p + 8);
    float2 v3 = *(const float2*)(p + 8 * (size_t)ND + 8);
    __half2 q0 = __floats2half2_rn(v0.x, v0.y);
    __half2 q1 = __floats2half2_rn(v1.x, v1.y);
    __half2 q2 = __floats2half2_rn(v2.x, v2.y);
    __half2 q3 = __floats2half2_rn(v3.x, v3.y);
    f[0] = *(uint32_t*)&q0; f[1] = *(uint32_t*)&q1;
    f[2] = *(uint32_t*)&q2; f[3] = *(uint32_t*)&q3;
}

__global__ __launch_bounds__(NTHREADS, 1) void rnn_kernel(
    const float* __restrict__ inp,   // [NS, TT, ND]
    const float* __restrict__ A,     // [ND, ND]
    const float* __restrict__ h0,    // [NS, ND]
    float* __restrict__ out)         // [NS, TT, ND]
{
    __shared__ float psum1[NWARPS][SBLK * ROWBLK];  // 16 KB
    __shared__ float psum2[NWARPS][SBLK * ROWBLK];  // 16 KB

    const int tid  = threadIdx.x;
    const int w    = tid >> 5;
    const int lane = tid & 31;
    const int g    = lane >> 2;
    const int tig  = lane & 3;

    const int cta  = blockIdx.x;
    const int rb   = cta >> 1;
    const int sb   = cta & 1;
    const int row0 = rb * ROWBLK;
    const int s0   = sb * SBLK;

    // ---- Resident A fragments ----
    uint32_t afrag[KTILES][2][4];
#pragma unroll
    for (int kt = 0; kt < KTILES; kt++) {
        int k0 = (w * KTILES + kt) * 16 + 2 * tig;
        load_afrag(afrag[kt][0], A, row0 + g, k0);
        load_afrag(afrag[kt][1], A, row0 + 16 + g, k0);
    }

    // ================= Phase 1: compute A2 = A @ A (rows of this rb) ======
    // Only sb==0 CTAs compute; result goes to g_A2 (fp32).
    if (sb == 0) {
        // warp w handles j-blocks w, w+8, ..., w+120 (full-k sweep each).
        for (int jj = 0; jj < 16; jj++) {
            int jblk = w + jj * NWARPS;
            int j    = jblk * 8 + g;
            float d[2][4];
#pragma unroll
            for (int m = 0; m < 2; m++)
#pragma unroll
                for (int c = 0; c < 4; c++) d[m][c] = 0.0f;
            for (int kt = 0; kt < 64; kt++) {
                int kb = kt * 16 + 2 * tig;
                // B[k, j] = A[k, j]; column loads (scalar).
                float e0 = A[(size_t)(kb)     * ND + j];
                float e1 = A[(size_t)(kb + 1) * ND + j];
                float e2 = A[(size_t)(kb + 8) * ND + j];
                float e3 = A[(size_t)(kb + 9) * ND + j];
                __half2 hb0 = __floats2half2_rn(e0, e1);
                __half2 hb1 = __floats2half2_rn(e2, e3);
                uint32_t b0 = *(uint32_t*)&hb0;
                uint32_t b1 = *(uint32_t*)&hb1;
                // A-operand frag for this kt: need afrag index: kt spans full K,
                // owned warp-partitioned; recompute from A directly.
                uint32_t af0[4], af1[4];
                load_afrag(af0, A, row0 + g,      kt * 16 + 2 * tig);
                load_afrag(af1, A, row0 + 16 + g, kt * 16 + 2 * tig);
                mma16816(d[0], af0, b0, b1);
                mma16816(d[1], af1, b0, b1);
            }
#pragma unroll
            for (int m = 0; m < 2; m++)
#pragma unroll
                for (int c = 0; c < 4; c++) {
                    int i  = row0 + m * 16 + g + ((c >> 1) << 3);
                    int jc = jblk * 8 + tig * 2 + (c & 1);
                    g_A2[(size_t)i * ND + jc] = d[m][c];
                }
        }
    }
    grid_barrier();

    // ---- Resident A^2 fragments ----
    uint32_t a2frag[KTILES][2][4];
#pragma unroll
    for (int kt = 0; kt < KTILES; kt++) {
        int k0 = (w * KTILES + kt) * 16 + 2 * tig;
        load_afrag(a2frag[kt][0], g_A2, row0 + g, k0);
        load_afrag(a2frag[kt][1], g_A2, row0 + 16 + g, k0);
    }

    // ---- Per-thread state ownership ----
    const int s_l  = tid >> 4;
    const int i_l  = (tid & 15) << 1;
    const int s_gl = s0 + s_l;
    const int i_gl = row0 + i_l;
    const int e    = s_l * ROWBLK + i_l;

    const float* inp_base = inp + (size_t)s_gl * TT * ND + i_gl;
    float* out_base       = out + (size_t)s_gl * TT * ND + i_gl;

    // ---- Production 0: h0 ----
    float2 hprev = *(const float2*)(h0 + (size_t)s_gl * ND + i_gl);
    *(float2*)out_base = hprev;
    {
        __half2 hh = __floats2half2_rn(hprev.x, hprev.y);
        *(__half2*)&g_hbuf[0][s_gl * ND + hpos(i_gl)] = hh;
    }
    __syncthreads();
    if (tid == 0) flag_release(&g_flags[sb][rb], 1u);

    // x-fragment base pointers for the q GEMM (per nu).
    const float* xq_base[2];
#pragma unroll
    for (int nu = 0; nu < 2; nu++)
        xq_base[nu] = inp + (size_t)(s0 + nu * 8 + g) * TT * ND;

    // ================= Main loop: 1023 double-steps =================
    for (int s = 0; s < (TT - 2) / 2; s++) {
        const int ts = 2 * s;   // computes h[ts+1], h[ts+2] from h[ts]

        // Own-element x values (needed at the end).
        float2 xa = __ldcs((const float2*)(inp_base + (size_t)ts * ND));
        float2 xb = __ldcs((const float2*)(inp_base + (size_t)(ts + 1) * ND));

        float d1[2][2][4];   // A h
        float d2[2][2][4];   // A^2 h + A x (both carry alpha^2)
#pragma unroll
        for (int m = 0; m < 2; m++)
#pragma unroll
            for (int nu = 0; nu < 2; nu++)
#pragma unroll
                for (int c = 0; c < 4; c++) { d1[m][nu][c] = 0.f; d2[m][nu][c] = 0.f; }

        // ---- q = A x_ts : dependency-free, issued BEFORE the wait ----
#pragma unroll
        for (int kt = 0; kt < KTILES; kt++) {
            int kb = (w * KTILES + kt) * 16 + 2 * tig;
#pragma unroll
            for (int nu = 0; nu < 2; nu++) {
                const float* xp = xq_base[nu] + (size_t)ts * ND + kb;
                float2 v0 = __ldcs((const float2*)xp);
                float2 v1 = __ldcs((const float2*)(xp + 8));
                __half2 hq0 = __floats2half2_rn(v0.x, v0.y);
                __half2 hq1 = __floats2half2_rn(v1.x, v1.y);
                uint32_t b0 = *(uint32_t*)&hq0;
                uint32_t b1 = *(uint32_t*)&hq1;
                mma16816(d2[0][nu], afrag[kt][0], b0, b1);
                mma16816(d2[1][nu], afrag[kt][1], b0, b1);
            }
        }

        // ---- Wait: warp 0 polls all 32 producers, then CTA-wide release ----
        if (w == 0) {
            const volatile unsigned* f = &g_flags[sb][lane];
            unsigned v = flag_acquire(f);
            while (__ballot_sync(0xffffffffu, v < (unsigned)(s + 1))) {
                if (v < (unsigned)(s + 1)) v = flag_acquire(f);
            }
        }
        __syncthreads();

        const __half* hb = g_hbuf[s & 1];

        // ---- p1 = A h, p2 += A^2 h (shared B fragments) ----
#pragma unroll
        for (int kt = 0; kt < KTILES; kt++) {
            int koff = (w * KTILES + kt) * 16 + tig * 4;
#pragma unroll
            for (int nu = 0; nu < 2; nu++) {
                int smp = s0 + nu * 8 + g;
                uint2 b = *(const uint2*)(hb + (size_t)smp * ND + koff);
                mma16816(d1[0][nu], afrag[kt][0],  b.x, b.y);
                mma16816(d1[1][nu], afrag[kt][1],  b.x, b.y);
                mma16816(d2[0][nu], a2frag[kt][0], b.x, b.y);
                mma16816(d2[1][nu], a2frag[kt][1], b.x, b.y);
            }
        }

        // ---- cross-warp reduction ----
#pragma unroll
        for (int m = 0; m < 2; m++)
#pragma unroll
            for (int nu = 0; nu < 2; nu++)
#pragma unroll
                for (int c = 0; c < 4; c++) {
                    int i_loc = m * 16 + g + ((c >> 1) << 3);
                    int s_loc = nu * 8 + tig * 2 + (c & 1);
                    psum1[w][s_loc * ROWBLK + i_loc] = d1[m][nu][c];
                    psum2[w][s_loc * ROWBLK + i_loc] = d2[m][nu][c];
                }
        __syncthreads();

        float P1x = 0.f, P1y = 0.f, D2x = 0.f, D2y = 0.f;
#pragma unroll
        for (int ww = 0; ww < NWARPS; ww++) {
            float2 p = *(const float2*)&psum1[ww][e];
            float2 q = *(const float2*)&psum2[ww][e];
            P1x += p.x; P1y += p.y; D2x += q.x; D2y += q.y;
        }

        float h1x = BETA * hprev.x + ALPHA * (P1x + xa.x);
        float h1y = BETA * hprev.y + ALPHA * (P1y + xa.y);
        float h2x = BETA * h1x + ABC * P1x + A2C * D2x + ALPHA * xb.x;
        float h2y = BETA * h1y + ABC * P1y + A2C * D2y + ALPHA * xb.y;
        hprev.x = h2x; hprev.y = h2y;

        __stcs((float2*)(out_base + (size_t)(ts + 1) * ND), make_float2(h1x, h1y));
        __stcs((float2*)(out_base + (size_t)(ts + 2) * ND), make_float2(h2x, h2y));

        __half2 hh = __floats2half2_rn(h2x, h2y);
        *(__half2*)&g_hbuf[(s + 1) & 1][s_gl * ND + hpos(i_gl)] = hh;

        __syncthreads();
        if (tid == 0) flag_release(&g_flags[sb][rb], (unsigned)(s + 2));
    }

    // ================= Epilogue: final single step t = TT-1 =================
    {
        const int s = (TT - 2) / 2;          // 1023
        const int ts = 2 * s;                // 2046
        float2 xa = __ldcs((const float2*)(inp_base + (size_t)ts * ND));

        if (w == 0) {
            const volatile unsigned* f = &g_flags[sb][lane];
            unsigned v = flag_acquire(f);
            while (__ballot_sync(0xffffffffu, v < (unsigned)(s + 1))) {
                if (v < (unsigned)(s + 1)) v = flag_acquire(f);
            }
        }
        __syncthreads();

        const __half* hb = g_hbuf[s & 1];
        float d1[2][2][4];
#pragma unroll
        for (int m = 0; m < 2; m++)
#pragma unroll
            for (int nu = 0; nu < 2; nu++)
#pragma unroll
                for (int c = 0; c < 4; c++) d1[m][nu][c] = 0.f;

#pragma unroll
        for (int kt = 0; kt < KTILES; kt++) {
            int koff = (w * KTILES + kt) * 16 + tig * 4;
#pragma unroll
            for (int nu = 0; nu < 2; nu++) {
                int smp = s0 + nu * 8 + g;
                uint2 b = *(const uint2*)(hb + (size_t)smp * ND + koff);
                mma16816(d1[0][nu], afrag[kt][0], b.x, b.y);
                mma16816(d1[1][nu], afrag[kt][1], b.x, b.y);
            }
        }
#pragma unroll
        for (int m = 0; m < 2; m++)
#pragma unroll
            for (int nu = 0; nu < 2; nu++)
#pragma unroll
                for (int c = 0; c < 4; c++) {
                    int i_loc = m * 16 + g + ((c >> 1) << 3);
                    int s_loc = nu * 8 + tig * 2 + (c & 1);
                    psum1[w][s_loc * ROWBLK + i_loc] = d1[m][nu][c];
                }
        __syncthreads();

        float P1x = 0.f, P1y = 0.f;
#pragma unroll
        for (int ww = 0; ww < NWARPS; ww++) {
            float2 p = *(const float2*)&psum1[ww][e];
            P1x += p.x; P1y += p.y;
        }
        float h1x = BETA * hprev.x + ALPHA * (P1x + xa.x);
        float h1y = BETA * hprev.y + ALPHA * (P1y + xa.y);
        __stcs((float2*)(out_base + (size_t)(ts + 1) * ND), make_float2(h1x, h1y));
    }

    // ---- Cleanup so graph replays start from flags == 0 ----
    grid_barrier();
    if (tid == 0) g_flags[sb][rb] = 0u;
}

extern "C" void kernel_launch(void* const* d_in, const int* in_sizes, int n_in,
                              void* d_out, int out_size) {
    const float* inp = (const float*)d_in[0];
    const float* A   = (const float*)d_in[1];
    const float* h0  = (const float*)d_in[2];
    float* out       = (float*)d_out;
    rnn_kernel<<<GRID, NTHREADS>>>(inp, A, h0, out);
}

// round 6
// speedup vs baseline: 4.3736x; 1.5130x over previous
#include <cuda_runtime.h>
#include <cuda_fp16.h>
#include <stdint.h>

#define NS 32
#define TT 2048
#define ND 1024
#define GRID 128
#define NTHREADS 256
#define NWARPS 8
#define KTILES 8     // 8 warps * 8 ktiles * 16 = 1024 = K
#define ROWBLK 32    // A rows per CTA
#define SBLK 8       // samples per CTA
#define SGROUPS 4

#define ALPHA 0.1f
#define BETA  0.9f
#define A2C   (ALPHA * ALPHA)
#define ABC   (ALPHA * BETA)

// Double-buffered fp16 hidden state, pre-swizzled mma-B layout.
__device__ __align__(16) __half g_hbuf[2][NS * ND];
// A@A (row-major fp32), computed once per launch in phase 1.
__device__ float g_A2[ND * ND];
// Producer flags: g_flags[sb][rb] = completed productions by CTA (rb, sb).
__device__ __align__(256) volatile unsigned g_flags[SGROUPS][32];
// Sense-reversing grid barrier (phase transitions + cleanup only).
__device__ unsigned g_bar_count;
__device__ unsigned g_bar_gen;

__device__ __forceinline__ void grid_barrier() {
    __syncthreads();
    if (threadIdx.x == 0) {
        unsigned gen = *((volatile unsigned*)&g_bar_gen);
        __threadfence();
        unsigned old = atomicAdd(&g_bar_count, 1u);
        if (old == GRID - 1) {
            g_bar_count = 0;
            __threadfence();
            atomicExch(&g_bar_gen, gen + 1u);
        } else {
            while (*((volatile unsigned*)&g_bar_gen) == gen) { }
        }
        __threadfence();
    }
    __syncthreads();
}

__device__ __forceinline__ void mma16816(float* d, const uint32_t* a,
                                         uint32_t b0, uint32_t b1) {
    asm volatile(
        "mma.sync.aligned.m16n8k16.row.col.f32.f16.f16.f32 "
        "{%0,%1,%2,%3}, {%4,%5,%6,%7}, {%8,%9}, {%0,%1,%2,%3};\n"
        : "+f"(d[0]), "+f"(d[1]), "+f"(d[2]), "+f"(d[3])
        : "r"(a[0]), "r"(a[1]), "r"(a[2]), "r"(a[3]), "r"(b0), "r"(b1));
}

// Swizzled position of logical element j (per 16-block order 0,1,8,9,2,3,...).
__device__ __forceinline__ int hpos(int j) {
    int r = j & 15;
    return (j & ~15) + ((r & 6) << 1) + ((r >> 3) << 1) + (r & 1);
}

__device__ __forceinline__ unsigned flag_acquire(const volatile unsigned* p) {
    unsigned v;
    asm volatile("ld.global.acquire.gpu.u32 %0, [%1];"
                 : "=r"(v) : "l"((const unsigned*)p) : "memory");
    return v;
}

__device__ __forceinline__ void flag_release(volatile unsigned* p, unsigned v) {
    asm volatile("st.global.release.gpu.u32 [%0], %1;"
                 :: "l"((unsigned*)p), "r"(v) : "memory");
}

__device__ __forceinline__ void load_afrag(uint32_t* f, const float* src,
                                           int row, int k0) {
    const float* p = src + (size_t)row * ND + k0;
    float2 v0 = *(const float2*)(p);
    float2 v1 = *(const float2*)(p + 8 * (size_t)ND);
    float2 v2 = *(const float2*)(p + 8);
    float2 v3 = *(const float2*)(p + 8 * (size_t)ND + 8);
    __half2 q0 = __floats2half2_rn(v0.x, v0.y);
    __half2 q1 = __floats2half2_rn(v1.x, v1.y);
    __half2 q2 = __floats2half2_rn(v2.x, v2.y);
    __half2 q3 = __floats2half2_rn(v3.x, v3.y);
    f[0] = *(uint32_t*)&q0; f[1] = *(uint32_t*)&q1;
    f[2] = *(uint32_t*)&q2; f[3] = *(uint32_t*)&q3;
}

__global__ __launch_bounds__(NTHREADS, 1) void rnn_kernel(
    const float* __restrict__ inp,   // [NS, TT, ND]
    const float* __restrict__ A,     // [ND, ND]
    const float* __restrict__ h0,    // [NS, ND]
    float* __restrict__ out)         // [NS, TT, ND]
{
    __shared__ float psum1[NWARPS][SBLK * ROWBLK];  // 8 KB
    __shared__ float psum2[NWARPS][SBLK * ROWBLK];  // 8 KB

    const int tid  = threadIdx.x;
    const int w    = tid >> 5;
    const int lane = tid & 31;
    const int g    = lane >> 2;
    const int tig  = lane & 3;

    const int cta  = blockIdx.x;
    const int rb   = cta >> 2;        // 32 row blocks
    const int sb   = cta & 3;         // 4 sample groups
    const int row0 = rb * ROWBLK;
    const int s0   = sb * SBLK;

    // ---- Resident A fragments (k-split across warps) ----
    uint32_t afrag[KTILES][2][4];
#pragma unroll
    for (int kt = 0; kt < KTILES; kt++) {
        int k0 = (w * KTILES + kt) * 16 + 2 * tig;
        load_afrag(afrag[kt][0], A, row0 + g, k0);
        load_afrag(afrag[kt][1], A, row0 + 16 + g, k0);
    }

    // ========== Phase 1: A2 = A @ A, all 128 CTAs, j-split by sb ==========
    // CTA (rb, sb) computes rows [row0, row0+32) x jblocks [sb*32, sb*32+32).
    for (int jj = 0; jj < 32; jj++) {
        const int jblk = sb * 32 + jj;
        const int j    = jblk * 8 + g;
        float d[2][4];
#pragma unroll
        for (int m = 0; m < 2; m++)
#pragma unroll
            for (int c = 0; c < 4; c++) d[m][c] = 0.0f;

#pragma unroll
        for (int kt = 0; kt < KTILES; kt++) {
            const int kb = (w * KTILES + kt) * 16;
            float e0 = A[(size_t)(kb + 2 * tig)     * ND + j];
            float e1 = A[(size_t)(kb + 2 * tig + 1) * ND + j];
            float e2 = A[(size_t)(kb + 2 * tig + 8) * ND + j];
            float e3 = A[(size_t)(kb + 2 * tig + 9) * ND + j];
            __half2 hb0 = __floats2half2_rn(e0, e1);
            __half2 hb1 = __floats2half2_rn(e2, e3);
            uint32_t b0 = *(uint32_t*)&hb0;
            uint32_t b1 = *(uint32_t*)&hb1;
            mma16816(d[0], afrag[kt][0], b0, b1);
            mma16816(d[1], afrag[kt][1], b0, b1);
        }
        // reduce across warps through psum1: slot = j_loc * ROWBLK + i_loc
#pragma unroll
        for (int m = 0; m < 2; m++)
#pragma unroll
            for (int c = 0; c < 4; c++) {
                int i_loc = m * 16 + g + ((c >> 1) << 3);
                int j_loc = tig * 2 + (c & 1);
                psum1[w][j_loc * ROWBLK + i_loc] = d[m][c];
            }
        __syncthreads();
        {
            int i_loc = tid & 31;
            int j_loc = tid >> 5;
            float s = 0.f;
#pragma unroll
            for (int ww = 0; ww < NWARPS; ww++)
                s += psum1[ww][j_loc * ROWBLK + i_loc];
            g_A2[(size_t)(row0 + i_loc) * ND + jblk * 8 + j_loc] = s;
        }
        __syncthreads();
    }
    grid_barrier();

    // ---- Resident A^2 fragments ----
    uint32_t a2frag[KTILES][2][4];
#pragma unroll
    for (int kt = 0; kt < KTILES; kt++) {
        int k0 = (w * KTILES + kt) * 16 + 2 * tig;
        load_afrag(a2frag[kt][0], g_A2, row0 + g, k0);
        load_afrag(a2frag[kt][1], g_A2, row0 + 16 + g, k0);
    }

    // ---- Per-thread state ownership: 1 element each ----
    const int s_l  = tid >> 5;            // 0..7
    const int i_l  = tid & 31;            // 0..31
    const int s_gl = s0 + s_l;
    const int i_gl = row0 + i_l;
    const int e    = s_l * ROWBLK + i_l;

    const float* inp_base = inp + (size_t)s_gl * TT * ND + i_gl;
    float* out_base       = out + (size_t)s_gl * TT * ND + i_gl;
    const int hslot = s_gl * ND + hpos(i_gl);

    // ---- Production 0: h0 ----
    float hprev = h0[(size_t)s_gl * ND + i_gl];
    out_base[0] = hprev;
    g_hbuf[0][hslot] = __float2half_rn(hprev);
    __syncthreads();
    if (tid == 0) flag_release(&g_flags[sb][rb], 1u);

    // x base for the Q GEMM (B operand rows = samples s0+g).
    const float* xq_base = inp + (size_t)(s0 + g) * TT * ND;

    // ================= Main loop: 1023 double-steps =================
    for (int s = 0; s < (TT - 2) / 2; s++) {
        const int ts = 2 * s;   // produces h[ts+1], h[ts+2] from h[ts]

        float xa = __ldcs(inp_base + (size_t)ts * ND);
        float xb = __ldcs(inp_base + (size_t)(ts + 1) * ND);

        float d1[2][4];   // A h
        float d2[2][4];   // A^2 h + A x_ts   (both carry alpha^2)
#pragma unroll
        for (int m = 0; m < 2; m++)
#pragma unroll
            for (int c = 0; c < 4; c++) { d1[m][c] = 0.f; d2[m][c] = 0.f; }

        // ---- Q = A x_ts : dependency-free, issued before the wait ----
#pragma unroll
        for (int kt = 0; kt < KTILES; kt++) {
            int kb = (w * KTILES + kt) * 16 + 2 * tig;
            const float* xp = xq_base + (size_t)ts * ND + kb;
            float2 v0 = __ldcs((const float2*)xp);
            float2 v1 = __ldcs((const float2*)(xp + 8));
            __half2 hq0 = __floats2half2_rn(v0.x, v0.y);
            __half2 hq1 = __floats2half2_rn(v1.x, v1.y);
            uint32_t b0 = *(uint32_t*)&hq0;
            uint32_t b1 = *(uint32_t*)&hq1;
            mma16816(d2[0], afrag[kt][0], b0, b1);
            mma16816(d2[1], afrag[kt][1], b0, b1);
        }

        // ---- Wait: warp 0 polls all 32 producers of this group ----
        if (w == 0) {
            const volatile unsigned* f = &g_flags[sb][lane];
            unsigned v = flag_acquire(f);
            while (__ballot_sync(0xffffffffu, v < (unsigned)(s + 1))) {
                if (v < (unsigned)(s + 1)) v = flag_acquire(f);
            }
        }
        __syncthreads();

        const __half* hb = g_hbuf[s & 1];

        // ---- P1 = A h, P2 += A^2 h (shared B fragments) ----
#pragma unroll
        for (int kt = 0; kt < KTILES; kt++) {
            int koff = (w * KTILES + kt) * 16 + tig * 4;
            uint2 b = *(const uint2*)(hb + (size_t)(s0 + g) * ND + koff);
            mma16816(d1[0], afrag[kt][0],  b.x, b.y);
            mma16816(d1[1], afrag[kt][1],  b.x, b.y);
            mma16816(d2[0], a2frag[kt][0], b.x, b.y);
            mma16816(d2[1], a2frag[kt][1], b.x, b.y);
        }

        // ---- cross-warp reduction ----
#pragma unroll
        for (int m = 0; m < 2; m++)
#pragma unroll
            for (int c = 0; c < 4; c++) {
                int i_loc = m * 16 + g + ((c >> 1) << 3);
                int s_loc = tig * 2 + (c & 1);
                psum1[w][s_loc * ROWBLK + i_loc] = d1[m][c];
                psum2[w][s_loc * ROWBLK + i_loc] = d2[m][c];
            }
        __syncthreads();

        float P1 = 0.f, D2 = 0.f;
#pragma unroll
        for (int ww = 0; ww < NWARPS; ww++) {
            P1 += psum1[ww][e];
            D2 += psum2[ww][e];
        }

        float h1 = BETA * hprev + ALPHA * (P1 + xa);
        float h2 = BETA * h1 + ABC * P1 + A2C * D2 + ALPHA * xb;
        hprev = h2;

        __stcs(out_base + (size_t)(ts + 1) * ND, h1);
        __stcs(out_base + (size_t)(ts + 2) * ND, h2);
        g_hbuf[(s + 1) & 1][hslot] = __float2half_rn(h2);

        __syncthreads();
        if (tid == 0) flag_release(&g_flags[sb][rb], (unsigned)(s + 2));
    }

    // ================= Epilogue: final single step t = TT-1 =================
    {
        const int s  = (TT - 2) / 2;   // 1023
        const int ts = 2 * s;          // 2046
        float xa = __ldcs(inp_base + (size_t)ts * ND);

        if (w == 0) {
            const volatile unsigned* f = &g_flags[sb][lane];
            unsigned v = flag_acquire(f);
            while (__ballot_sync(0xffffffffu, v < (unsigned)(s + 1))) {
                if (v < (unsigned)(s + 1)) v = flag_acquire(f);
            }
        }
        __syncthreads();

        const __half* hb = g_hbuf[s & 1];
        float d1[2][4];
#pragma unroll
        for (int m = 0; m < 2; m++)
#pragma unroll
            for (int c = 0; c < 4; c++) d1[m][c] = 0.f;

#pragma unroll
        for (int kt = 0; kt < KTILES; kt++) {
            int koff = (w * KTILES + kt) * 16 + tig * 4;
            uint2 b = *(const uint2*)(hb + (size_t)(s0 + g) * ND + koff);
            mma16816(d1[0], afrag[kt][0], b.x, b.y);
            mma16816(d1[1], afrag[kt][1], b.x, b.y);
        }
#pragma unroll
        for (int m = 0; m < 2; m++)
#pragma unroll
            for (int c = 0; c < 4; c++) {
                int i_loc = m * 16 + g + ((c >> 1) << 3);
                int s_loc = tig * 2 + (c & 1);
                psum1[w][s_loc * ROWBLK + i_loc] = d1[m][c];
            }
        __syncthreads();

        float P1 = 0.f;
#pragma unroll
        for (int ww = 0; ww < NWARPS; ww++) P1 += psum1[ww][e];

        float h1 = BETA * hprev + ALPHA * (P1 + xa);
        __stcs(out_base + (size_t)(ts + 1) * ND, h1);
    }

    // ---- Cleanup so graph replays start from flags == 0 ----
    grid_barrier();
    if (tid == 0) g_flags[sb][rb] = 0u;
}

extern "C" void kernel_launch(void* const* d_in, const int* in_sizes, int n_in,
                              void* d_out, int out_size) {
    const float* inp = (const float*)d_in[0];
    const float* A   = (const float*)d_in[1];
    const float* h0  = (const float*)d_in[2];
    float* out       = (float*)d_out;
    rnn_kernel<<<GRID, NTHREADS>>>(inp, A, h0, out);
}